// round 16
// baseline (speedup 1.0000x reference)
#include <cuda_runtime.h>

// Problem constants (fixed shapes from reference setup_inputs)
#define BATCH 4
#define NPTS  8192
#define CH    32      // input channels
#define KNN   16      // neighbors
#define LDIM  64      // hidden (dense)
#define ODIM  128     // output channels
#define TILE  128     // candidate tile (== TPB)
#define TPB   128     // threads per block = queries per block
#define SPLIT 2       // candidate-range split (occupancy lever)
#define CSPAN (NPTS / SPLIT)   // candidates per phase-A block: 4096

// ---------------- device scratch (no allocs allowed) ----------------
__device__ float g_Wf[CH * ODIM];          // fused W_lin @ W_conv  [32,128]
__device__ float g_bf[ODIM];               // fused bias            [128]
__device__ float g_sq[BATCH * NPTS];       // per-point squared norms
__device__ float g_pd[BATCH * NPTS * SPLIT * KNN];  // partial top-16 dists (4 MB)
__device__ int   g_pi[BATCH * NPTS * SPLIT * KNN];  // partial top-16 idx   (4 MB)

// ---------------- packed f32x2 helpers ----------------
__device__ __forceinline__ void fma2(unsigned long long& acc,
                                     unsigned long long a,
                                     unsigned long long b) {
    asm("fma.rn.f32x2 %0, %1, %2, %3;" : "=l"(acc) : "l"(a), "l"(b), "l"(acc));
}
__device__ __forceinline__ float hsum2(unsigned long long v) {
    float lo, hi;
    asm("mov.b64 {%0, %1}, %2;" : "=f"(lo), "=f"(hi) : "l"(v));
    return lo + hi;
}

// sorted-ascending top-16 insertion (strict <: ties keep earlier-inserted,
// i.e. lower index, matching the reference). Fully unrolled -> registers.
__device__ __forceinline__ void bubble16(float (&bd)[KNN], int (&bi)[KNN],
                                         float d, int id) {
#pragma unroll
    for (int r = 0; r < KNN; ++r) {
        float od = bd[r];
        int   oi = bi[r];
        bool  sw = d < od;
        bd[r] = sw ? d  : od;
        bi[r] = sw ? id : oi;
        d  = sw ? od : d;
        id = sw ? oi : id;
    }
}

// ---------------- prep: fuse the two linear layers (parallel) ----------------
// out = relu(pooled @ (W_lin@W_conv) + (b_lin@W_conv + b_conv))
__global__ void prep_weights(const float* __restrict__ W_lin,
                             const float* __restrict__ b_lin,
                             const float* __restrict__ W_conv,
                             const float* __restrict__ b_conv) {
    __shared__ float s_wl[LDIM];
    const int c = blockIdx.x;
    const int o = threadIdx.x;
    if (o < LDIM) s_wl[o] = W_lin[c * LDIM + o];
    __syncthreads();
    float acc = 0.f;
#pragma unroll
    for (int l = 0; l < LDIM; ++l)
        acc = fmaf(s_wl[l], W_conv[l * ODIM + o], acc);
    g_Wf[c * ODIM + o] = acc;
    if (c == 0) {
        float bb = b_conv[o];
#pragma unroll
        for (int l = 0; l < LDIM; ++l)
            bb = fmaf(b_lin[l], W_conv[l * ODIM + o], bb);
        g_bf[o] = bb;
    }
}

// ---------------- prep: squared norms ----------------
__global__ void prep_sq(const float* __restrict__ x) {
    int p = blockIdx.x * blockDim.x + threadIdx.x;   // 0 .. BATCH*NPTS-1
    const float4* xp = reinterpret_cast<const float4*>(x + (size_t)p * CH);
    float s = 0.f;
#pragma unroll
    for (int i = 0; i < CH / 4; ++i) {
        float4 v = xp[i];
        s += v.x * v.x + v.y * v.y + v.z * v.z + v.w * v.w;
    }
    g_sq[p] = s;
}

// ---------------- phase A: partial KNN over half the candidates --------------
// One thread = one query. Score: sq_j - 2*dot(x_i,x_j) (per-query constant
// sq_i dropped; ordering identical). Deferred insertion: qualifying
// candidates are stashed branch-free in a 1-entry pending buffer; the
// expensive sorted-insert branch fires only on a second qualify (rate ~4p
// instead of ~32p per warp in the tail).
__global__ __launch_bounds__(TPB, 4)
void knn_partial(const float* __restrict__ x) {
    __shared__ float4 s_cand[TILE * (CH / 4)];   // 16 KB candidate tile
    __shared__ float  s_sq[TILE];

    const int blocks_per_batch = (NPTS / TPB) * SPLIT;   // 128
    const int b   = blockIdx.x / blocks_per_batch;
    const int rem = blockIdx.x % blocks_per_batch;
    const int q0  = (rem / SPLIT) * TPB;
    const int s   = rem % SPLIT;
    const int t   = threadIdx.x;
    const int q   = q0 + t;
    const int jbase = s * CSPAN;
    const float* xb = x + (size_t)b * NPTS * CH;

    // load query features as 16 packed f32x2 registers
    unsigned long long q2[CH / 2];
    {
        const ulonglong2* qp =
            reinterpret_cast<const ulonglong2*>(xb + (size_t)q * CH);
#pragma unroll
        for (int i = 0; i < CH / 4; ++i) {
            ulonglong2 v = qp[i];
            q2[2 * i]     = v.x;
            q2[2 * i + 1] = v.y;
        }
    }

    // top-16 smallest scores, sorted ascending, in registers
    float best_d[KNN];
    int   best_i[KNN];
#pragma unroll
    for (int r = 0; r < KNN; ++r) { best_d[r] = INFINITY; best_i[r] = -1; }
    float worst = INFINITY;

    // deferred-insert pending buffer
    float pend_d = 0.f;
    int   pend_i = 0;
    bool  has_pend = false;

    const float* sqb = g_sq + b * NPTS;

    for (int j0 = jbase; j0 < jbase + CSPAN; j0 += TILE) {
        __syncthreads();   // previous tile fully consumed
        {
            const float4* src =
                reinterpret_cast<const float4*>(xb + (size_t)j0 * CH);
#pragma unroll
            for (int i = 0; i < TILE * (CH / 4) / TPB; ++i)
                s_cand[t + i * TPB] = src[t + i * TPB];
            s_sq[t] = sqb[j0 + t];                // TILE == TPB
        }
        __syncthreads();

        for (int jj = 0; jj < TILE; jj += 2) {
            const ulonglong2* cp0 =
                reinterpret_cast<const ulonglong2*>(&s_cand[jj * (CH / 4)]);
            const ulonglong2* cp1 =
                reinterpret_cast<const ulonglong2*>(&s_cand[(jj + 1) * (CH / 4)]);
            unsigned long long a0 = 0ull, a1 = 0ull;   // candidate jj
            unsigned long long c0 = 0ull, c1 = 0ull;   // candidate jj+1
#pragma unroll
            for (int i = 0; i < CH / 4; ++i) {
                ulonglong2 v0 = cp0[i];                 // broadcast LDS.128
                ulonglong2 v1 = cp1[i];
                fma2(a0, q2[2 * i],     v0.x);
                fma2(a1, q2[2 * i + 1], v0.y);
                fma2(c0, q2[2 * i],     v1.x);
                fma2(c1, q2[2 * i + 1], v1.y);
            }
            float score0 = fmaf(-2.f, hsum2(a0) + hsum2(a1), s_sq[jj]);
            float score1 = fmaf(-2.f, hsum2(c0) + hsum2(c1), s_sq[jj + 1]);

            // ---- candidate jj: deferred insert ----
            {
                const int  id    = j0 + jj;
                const bool qual  = score0 < worst;
                const bool flush = qual & has_pend;
                if (flush) {                      // rare warp branch
                    bubble16(best_d, best_i, pend_d, pend_i);
                    bubble16(best_d, best_i, score0, id);
                    worst = best_d[KNN - 1];
                    has_pend = false;
                }
                const bool stash = qual & !flush; // predicated, branch-free
                pend_d   = stash ? score0 : pend_d;
                pend_i   = stash ? id     : pend_i;
                has_pend = has_pend | stash;
            }
            // ---- candidate jj+1: deferred insert ----
            {
                const int  id    = j0 + jj + 1;
                const bool qual  = score1 < worst;
                const bool flush = qual & has_pend;
                if (flush) {
                    bubble16(best_d, best_i, pend_d, pend_i);
                    bubble16(best_d, best_i, score1, id);
                    worst = best_d[KNN - 1];
                    has_pend = false;
                }
                const bool stash = qual & !flush;
                pend_d   = stash ? score1 : pend_d;
                pend_i   = stash ? id     : pend_i;
                has_pend = has_pend | stash;
            }
        }
    }

    // final flush of any pending candidate
    if (has_pend) {
        bubble16(best_d, best_i, pend_d, pend_i);
    }

    // write sorted partial result
    const size_t base = ((size_t)(b * NPTS + q) * SPLIT + s) * KNN;
    float4* pd = reinterpret_cast<float4*>(g_pd + base);
    int4*   pi = reinterpret_cast<int4*>(g_pi + base);
#pragma unroll
    for (int r = 0; r < KNN / 4; ++r) {
        pd[r] = make_float4(best_d[4 * r], best_d[4 * r + 1],
                            best_d[4 * r + 2], best_d[4 * r + 3]);
        pi[r] = make_int4(best_i[4 * r], best_i[4 * r + 1],
                          best_i[4 * r + 2], best_i[4 * r + 3]);
    }
}

// ---------------- phase B: merge halves + gather + max-pool + fused MLP ------
__global__ __launch_bounds__(TPB)
void merge_gather_mlp(const float* __restrict__ x, float* __restrict__ out) {
    __shared__ float s_Wf[CH * ODIM];            // 16 KB fused weights
    __shared__ float s_bf[ODIM];

    const int blocks_per_batch = NPTS / TPB;     // 64
    const int b  = blockIdx.x / blocks_per_batch;
    const int q0 = (blockIdx.x % blocks_per_batch) * TPB;
    const int t  = threadIdx.x;
    const int q  = q0 + t;
    const float* xb = x + (size_t)b * NPTS * CH;

#pragma unroll
    for (int i = t; i < CH * ODIM; i += TPB) s_Wf[i] = g_Wf[i];
    s_bf[t] = g_bf[t];                            // ODIM == TPB
    __syncthreads();

    // load half-A as the working sorted top-16
    const size_t baseA = (size_t)(b * NPTS + q) * SPLIT * KNN;
    float best_d[KNN];
    int   best_i[KNN];
    {
        const float4* pd = reinterpret_cast<const float4*>(g_pd + baseA);
        const int4*   pi = reinterpret_cast<const int4*>(g_pi + baseA);
#pragma unroll
        for (int r = 0; r < KNN / 4; ++r) {
            float4 d4 = pd[r];  int4 i4 = pi[r];
            best_d[4 * r] = d4.x; best_d[4 * r + 1] = d4.y;
            best_d[4 * r + 2] = d4.z; best_d[4 * r + 3] = d4.w;
            best_i[4 * r] = i4.x; best_i[4 * r + 1] = i4.y;
            best_i[4 * r + 2] = i4.z; best_i[4 * r + 3] = i4.w;
        }
    }
    float worst = best_d[KNN - 1];

    // insert half-B (all its indices are larger -> strict < keeps the
    // reference's lower-index tie preference)
    {
        const float4* pd = reinterpret_cast<const float4*>(g_pd + baseA + KNN);
        const int4*   pi = reinterpret_cast<const int4*>(g_pi + baseA + KNN);
#pragma unroll
        for (int r4 = 0; r4 < KNN / 4; ++r4) {
            float4 d4 = pd[r4];  int4 i4 = pi[r4];
            float dv[4] = {d4.x, d4.y, d4.z, d4.w};
            int   iv[4] = {i4.x, i4.y, i4.z, i4.w};
#pragma unroll
            for (int u = 0; u < 4; ++u) {
                if (dv[u] < worst) {
                    bubble16(best_d, best_i, dv[u], iv[u]);
                    worst = best_d[KNN - 1];
                }
            }
        }
    }

    // gather neighbor features + max pool (L2-resident: 1 MB/batch)
    float pooled[CH];
#pragma unroll
    for (int c = 0; c < CH; ++c) pooled[c] = -INFINITY;
#pragma unroll
    for (int r = 0; r < KNN; ++r) {
        const float4* np =
            reinterpret_cast<const float4*>(xb + (size_t)best_i[r] * CH);
#pragma unroll
        for (int i = 0; i < CH / 4; ++i) {
            float4 v = __ldg(np + i);
            pooled[4 * i + 0] = fmaxf(pooled[4 * i + 0], v.x);
            pooled[4 * i + 1] = fmaxf(pooled[4 * i + 1], v.y);
            pooled[4 * i + 2] = fmaxf(pooled[4 * i + 2], v.z);
            pooled[4 * i + 3] = fmaxf(pooled[4 * i + 3], v.w);
        }
    }

    // fused MLP: out = relu(pooled @ Wf + bf), Wf broadcast from smem
    float* outp = out + ((size_t)b * NPTS + q) * ODIM;
#pragma unroll
    for (int o0 = 0; o0 < ODIM; o0 += 32) {
        float acc[32];
#pragma unroll
        for (int oi = 0; oi < 32; ++oi) acc[oi] = s_bf[o0 + oi];
#pragma unroll
        for (int c = 0; c < CH; ++c) {
            float p = pooled[c];
            const float4* wrow =
                reinterpret_cast<const float4*>(&s_Wf[c * ODIM + o0]);
#pragma unroll
            for (int i = 0; i < 8; ++i) {
                float4 w = wrow[i];
                acc[4 * i + 0] = fmaf(p, w.x, acc[4 * i + 0]);
                acc[4 * i + 1] = fmaf(p, w.y, acc[4 * i + 1]);
                acc[4 * i + 2] = fmaf(p, w.z, acc[4 * i + 2]);
                acc[4 * i + 3] = fmaf(p, w.w, acc[4 * i + 3]);
            }
        }
        float4* op = reinterpret_cast<float4*>(outp + o0);
#pragma unroll
        for (int i = 0; i < 8; ++i) {
            float4 v;
            v.x = fmaxf(acc[4 * i + 0], 0.f);
            v.y = fmaxf(acc[4 * i + 1], 0.f);
            v.z = fmaxf(acc[4 * i + 2], 0.f);
            v.w = fmaxf(acc[4 * i + 3], 0.f);
            op[i] = v;
        }
    }
}

extern "C" void kernel_launch(void* const* d_in, const int* in_sizes, int n_in,
                              void* d_out, int out_size) {
    const float* x      = (const float*)d_in[0];  // [B,N,C]
    const float* W_lin  = (const float*)d_in[1];  // [C,L]
    const float* b_lin  = (const float*)d_in[2];  // [L]
    const float* W_conv = (const float*)d_in[3];  // [L,O]
    const float* b_conv = (const float*)d_in[4];  // [O]
    float* out = (float*)d_out;                   // [B,N,O]

    (void)in_sizes; (void)n_in; (void)out_size;

    prep_weights<<<CH, ODIM>>>(W_lin, b_lin, W_conv, b_conv);
    prep_sq<<<(BATCH * NPTS) / 256, 256>>>(x);
    knn_partial<<<BATCH * (NPTS / TPB) * SPLIT, TPB>>>(x);
    merge_gather_mlp<<<BATCH * (NPTS / TPB), TPB>>>(x, out);
}

// round 17
// speedup vs baseline: 1.1147x; 1.1147x over previous
#include <cuda_runtime.h>

// Problem constants (fixed shapes from reference setup_inputs)
#define BATCH 4
#define NPTS  8192
#define CH    32      // input channels
#define KNN   16      // neighbors
#define LDIM  64      // hidden (dense)
#define ODIM  128     // output channels
#define TPB   128     // threads per block
#define SPLIT 2       // candidate-range split
#define CSPAN (NPTS / SPLIT)   // candidates per phase-A scan: 4096

// phase-A warp layout
#define QPW 16                 // queries per warp
#define WPB (TPB / 32)         // warps per block = 4
#define QPB (QPW * WPB)        // queries per block = 64
#define SUB 32                 // candidates per register batch (== warp size)

// ---------------- device scratch (no allocs allowed) ----------------
__device__ float g_Wf[CH * ODIM];          // fused W_lin @ W_conv  [32,128]
__device__ float g_bf[ODIM];               // fused bias            [128]
__device__ float g_sq[BATCH * NPTS];       // per-point squared norms
__device__ float g_pd[BATCH * NPTS * SPLIT * KNN];  // partial top-16 dists
__device__ int   g_pi[BATCH * NPTS * SPLIT * KNN];  // partial top-16 idx

// ---------------- packed f32x2 helpers ----------------
__device__ __forceinline__ void fma2(unsigned long long& acc,
                                     unsigned long long a,
                                     unsigned long long b) {
    asm("fma.rn.f32x2 %0, %1, %2, %3;" : "=l"(acc) : "l"(a), "l"(b), "l"(acc));
}
__device__ __forceinline__ void mul2(unsigned long long& d,
                                     unsigned long long a,
                                     unsigned long long b) {
    asm("mul.rn.f32x2 %0, %1, %2;" : "=l"(d) : "l"(a), "l"(b));
}
__device__ __forceinline__ void add2(unsigned long long& d,
                                     unsigned long long a,
                                     unsigned long long b) {
    asm("add.rn.f32x2 %0, %1, %2;" : "=l"(d) : "l"(a), "l"(b));
}
__device__ __forceinline__ float hsum2(unsigned long long v) {
    float lo, hi;
    asm("mov.b64 {%0, %1}, %2;" : "=f"(lo), "=f"(hi) : "l"(v));
    return lo + hi;
}

// sorted-ascending top-16 insertion for phase B (per-thread registers)
__device__ __forceinline__ void bubble16(float (&bd)[KNN], int (&bi)[KNN],
                                         float d, int id) {
#pragma unroll
    for (int r = 0; r < KNN; ++r) {
        float od = bd[r];
        int   oi = bi[r];
        bool  sw = d < od;
        bd[r] = sw ? d  : od;
        bi[r] = sw ? id : oi;
        d  = sw ? od : d;
        id = sw ? oi : id;
    }
}

// ---------------- prep: fuse the two linear layers (parallel) ----------------
__global__ void prep_weights(const float* __restrict__ W_lin,
                             const float* __restrict__ b_lin,
                             const float* __restrict__ W_conv,
                             const float* __restrict__ b_conv) {
    __shared__ float s_wl[LDIM];
    const int c = blockIdx.x;
    const int o = threadIdx.x;
    if (o < LDIM) s_wl[o] = W_lin[c * LDIM + o];
    __syncthreads();
    float acc = 0.f;
#pragma unroll
    for (int l = 0; l < LDIM; ++l)
        acc = fmaf(s_wl[l], W_conv[l * ODIM + o], acc);
    g_Wf[c * ODIM + o] = acc;
    if (c == 0) {
        float bb = b_conv[o];
#pragma unroll
        for (int l = 0; l < LDIM; ++l)
            bb = fmaf(b_lin[l], W_conv[l * ODIM + o], bb);
        g_bf[o] = bb;
    }
}

// ---------------- prep: squared norms ----------------
__global__ void prep_sq(const float* __restrict__ x) {
    int p = blockIdx.x * blockDim.x + threadIdx.x;
    const float4* xp = reinterpret_cast<const float4*>(x + (size_t)p * CH);
    float s = 0.f;
#pragma unroll
    for (int i = 0; i < CH / 4; ++i) {
        float4 v = xp[i];
        s += v.x * v.x + v.y * v.y + v.z * v.z + v.w * v.w;
    }
    g_sq[p] = s;
}

// ---------------- phase A: warp-cooperative partial KNN ----------------------
// Warp owns QPW=16 queries; lane owns one candidate per batch (regs, pre-scaled
// by -2). Score = sq_c - 2*dot(q,c) (per-query const sq_q dropped -> same order).
// Top-16 per query is DISTRIBUTED: lane r (r<16) holds rank-r (val,idx).
// Insertion is warp-uniform: ballot + shfl-based sorted insert, no divergence.
__global__ __launch_bounds__(TPB)
void knn_warp(const float* __restrict__ x) {
    __shared__ float s_q[QPB * CH];                 // 8 KB query features
    __shared__ float s_c[WPB][2][SUB * CH];         // 32 KB: per-warp dbl buf

    const int blocks_per_batch = (NPTS / QPB) * SPLIT;   // 256
    const int b   = blockIdx.x / blocks_per_batch;
    const int rem = blockIdx.x % blocks_per_batch;
    const int q0  = (rem / SPLIT) * QPB;
    const int s   = rem % SPLIT;
    const int t    = threadIdx.x;
    const int w    = t >> 5;
    const int lane = t & 31;
    const int jbase = s * CSPAN;
    const float* xb = x + (size_t)b * NPTS * CH;

    // stage this block's 64 query rows (plain row-major; reads are broadcast)
    {
        const float4* src = reinterpret_cast<const float4*>(xb + (size_t)q0 * CH);
        float4* dst = reinterpret_cast<float4*>(s_q);
#pragma unroll
        for (int m = t; m < QPB * CH / 4; m += TPB) dst[m] = src[m];
    }
    __syncthreads();

    // distributed top-16 state: lane r<16 holds rank-r entry of each query
    float lv[QPW];
    int   li[QPW];
    float wst[QPW];
#pragma unroll
    for (int qi = 0; qi < QPW; ++qi) { lv[qi] = INFINITY; li[qi] = 0; wst[qi] = INFINITY; }

    unsigned long long n2;   // packed (-2, -2)
    asm("mov.b64 %0, {%1, %2};" : "=l"(n2) : "f"(-2.0f), "f"(-2.0f));

    const float* sqb = g_sq + b * NPTS;
    const float* qbase = s_q + w * QPW * CH;

    for (int sub = 0; sub < CSPAN / SUB; ++sub) {
        const int j0 = jbase + sub * SUB;
        float* buf = s_c[w][sub & 1];

        // stage 32 candidate rows, coalesced gmem read, swizzled smem write
        {
            const float4* gsrc = reinterpret_cast<const float4*>(xb + (size_t)j0 * CH);
            float4* bw = reinterpret_cast<float4*>(buf);
#pragma unroll
            for (int i = 0; i < 8; ++i) {
                int m   = i * 32 + lane;          // linear float4 index, coalesced
                int row = m >> 3;
                int ch  = m & 7;
                bw[(row << 3) | (ch ^ (row & 7))] = gsrc[m];
            }
        }
        __syncwarp();

        // my candidate -> registers, pre-scaled by -2 (swizzled read, 4-phase)
        unsigned long long c2[CH / 2];
        {
            const ulonglong2* br = reinterpret_cast<const ulonglong2*>(buf);
#pragma unroll
            for (int i = 0; i < 8; ++i) {
                ulonglong2 v = br[(lane << 3) | (i ^ (lane & 7))];
                mul2(c2[2 * i],     v.x, n2);
                mul2(c2[2 * i + 1], v.y, n2);
            }
        }
        const float sqc = __ldg(&sqb[j0 + lane]);

        // 16 queries against my candidate; warp-uniform sorted inserts
#pragma unroll
        for (int qi = 0; qi < QPW; ++qi) {
            const ulonglong2* qp =
                reinterpret_cast<const ulonglong2*>(qbase + qi * CH);
            unsigned long long a0 = 0ull, a1 = 0ull;
#pragma unroll
            for (int i = 0; i < 8; ++i) {
                ulonglong2 qv = qp[i];            // broadcast LDS.128
                fma2(a0, qv.x, c2[2 * i]);
                fma2(a1, qv.y, c2[2 * i + 1]);
            }
            unsigned long long ss;
            add2(ss, a0, a1);
            const float score = sqc + hsum2(ss);

            unsigned bal = __ballot_sync(0xffffffffu, score < wst[qi]);
            while (bal) {                         // warp-uniform loop
                const int src = __ffs(bal) - 1;
                bal &= bal - 1;
                const float sc  = __shfl_sync(0xffffffffu, score, src);
                const int   sid = j0 + src;       // index derivable, no shfl
                // insert position: ties -> after existing (lower idx stays)
                const unsigned pb = __ballot_sync(0xffffffffu, lv[qi] <= sc);
                const int pos = __popc(pb);
                const float upv = __shfl_up_sync(0xffffffffu, lv[qi], 1);
                const int   upi = __shfl_up_sync(0xffffffffu, li[qi], 1);
                const bool shift = (lane > pos) && (lane < KNN);
                lv[qi] = shift ? upv : lv[qi];
                li[qi] = shift ? upi : li[qi];
                const bool take = (lane == pos) && (pos < KNN);
                lv[qi] = take ? sc  : lv[qi];
                li[qi] = take ? sid : li[qi];
                wst[qi] = __shfl_sync(0xffffffffu, lv[qi], KNN - 1);
            }
        }
    }

    // write sorted partial results: lane r writes rank r
    const int qg = q0 + w * QPW;
#pragma unroll
    for (int qi = 0; qi < QPW; ++qi) {
        if (lane < KNN) {
            const size_t base =
                ((size_t)(b * NPTS + qg + qi) * SPLIT + s) * KNN;
            g_pd[base + lane] = lv[qi];
            g_pi[base + lane] = li[qi];
        }
    }
}

// ---------------- phase B: merge halves + gather + max-pool + fused MLP ------
__global__ __launch_bounds__(TPB)
void merge_gather_mlp(const float* __restrict__ x, float* __restrict__ out) {
    __shared__ float s_Wf[CH * ODIM];
    __shared__ float s_bf[ODIM];

    const int blocks_per_batch = NPTS / TPB;
    const int b  = blockIdx.x / blocks_per_batch;
    const int q0 = (blockIdx.x % blocks_per_batch) * TPB;
    const int t  = threadIdx.x;
    const int q  = q0 + t;
    const float* xb = x + (size_t)b * NPTS * CH;

#pragma unroll
    for (int i = t; i < CH * ODIM; i += TPB) s_Wf[i] = g_Wf[i];
    s_bf[t] = g_bf[t];
    __syncthreads();

    const size_t baseA = (size_t)(b * NPTS + q) * SPLIT * KNN;
    float best_d[KNN];
    int   best_i[KNN];
    {
        const float4* pd = reinterpret_cast<const float4*>(g_pd + baseA);
        const int4*   pi = reinterpret_cast<const int4*>(g_pi + baseA);
#pragma unroll
        for (int r = 0; r < KNN / 4; ++r) {
            float4 d4 = pd[r];  int4 i4 = pi[r];
            best_d[4 * r] = d4.x; best_d[4 * r + 1] = d4.y;
            best_d[4 * r + 2] = d4.z; best_d[4 * r + 3] = d4.w;
            best_i[4 * r] = i4.x; best_i[4 * r + 1] = i4.y;
            best_i[4 * r + 2] = i4.z; best_i[4 * r + 3] = i4.w;
        }
    }
    float worst = best_d[KNN - 1];

    // insert half-B (indices all larger -> strict < keeps lower-index ties)
    {
        const float4* pd = reinterpret_cast<const float4*>(g_pd + baseA + KNN);
        const int4*   pi = reinterpret_cast<const int4*>(g_pi + baseA + KNN);
#pragma unroll
        for (int r4 = 0; r4 < KNN / 4; ++r4) {
            float4 d4 = pd[r4];  int4 i4 = pi[r4];
            float dv[4] = {d4.x, d4.y, d4.z, d4.w};
            int   iv[4] = {i4.x, i4.y, i4.z, i4.w};
#pragma unroll
            for (int u = 0; u < 4; ++u) {
                if (dv[u] < worst) {
                    bubble16(best_d, best_i, dv[u], iv[u]);
                    worst = best_d[KNN - 1];
                }
            }
        }
    }

    // gather neighbor features + max pool
    float pooled[CH];
#pragma unroll
    for (int c = 0; c < CH; ++c) pooled[c] = -INFINITY;
#pragma unroll
    for (int r = 0; r < KNN; ++r) {
        const float4* np =
            reinterpret_cast<const float4*>(xb + (size_t)best_i[r] * CH);
#pragma unroll
        for (int i = 0; i < CH / 4; ++i) {
            float4 v = __ldg(np + i);
            pooled[4 * i + 0] = fmaxf(pooled[4 * i + 0], v.x);
            pooled[4 * i + 1] = fmaxf(pooled[4 * i + 1], v.y);
            pooled[4 * i + 2] = fmaxf(pooled[4 * i + 2], v.z);
            pooled[4 * i + 3] = fmaxf(pooled[4 * i + 3], v.w);
        }
    }

    // fused MLP: out = relu(pooled @ Wf + bf)
    float* outp = out + ((size_t)b * NPTS + q) * ODIM;
#pragma unroll
    for (int o0 = 0; o0 < ODIM; o0 += 32) {
        float acc[32];
#pragma unroll
        for (int oi = 0; oi < 32; ++oi) acc[oi] = s_bf[o0 + oi];
#pragma unroll
        for (int c = 0; c < CH; ++c) {
            float p = pooled[c];
            const float4* wrow =
                reinterpret_cast<const float4*>(&s_Wf[c * ODIM + o0]);
#pragma unroll
            for (int i = 0; i < 8; ++i) {
                float4 wv = wrow[i];
                acc[4 * i + 0] = fmaf(p, wv.x, acc[4 * i + 0]);
                acc[4 * i + 1] = fmaf(p, wv.y, acc[4 * i + 1]);
                acc[4 * i + 2] = fmaf(p, wv.z, acc[4 * i + 2]);
                acc[4 * i + 3] = fmaf(p, wv.w, acc[4 * i + 3]);
            }
        }
        float4* op = reinterpret_cast<float4*>(outp + o0);
#pragma unroll
        for (int i = 0; i < 8; ++i) {
            float4 v;
            v.x = fmaxf(acc[4 * i + 0], 0.f);
            v.y = fmaxf(acc[4 * i + 1], 0.f);
            v.z = fmaxf(acc[4 * i + 2], 0.f);
            v.w = fmaxf(acc[4 * i + 3], 0.f);
            op[i] = v;
        }
    }
}

extern "C" void kernel_launch(void* const* d_in, const int* in_sizes, int n_in,
                              void* d_out, int out_size) {
    const float* x      = (const float*)d_in[0];  // [B,N,C]
    const float* W_lin  = (const float*)d_in[1];  // [C,L]
    const float* b_lin  = (const float*)d_in[2];  // [L]
    const float* W_conv = (const float*)d_in[3];  // [L,O]
    const float* b_conv = (const float*)d_in[4];  // [O]
    float* out = (float*)d_out;                   // [B,N,O]

    (void)in_sizes; (void)n_in; (void)out_size;

    prep_weights<<<CH, ODIM>>>(W_lin, b_lin, W_conv, b_conv);
    prep_sq<<<(BATCH * NPTS) / 256, 256>>>(x);
    knn_warp<<<BATCH * (NPTS / QPB) * SPLIT, TPB>>>(x);
    merge_gather_mlp<<<BATCH * (NPTS / TPB), TPB>>>(x, out);
}